// round 4
// baseline (speedup 1.0000x reference)
#include <cuda_runtime.h>
#include <cuda_bf16.h>
#include <math_constants.h>

#define B_      8
#define N_      8192
#define S_      2048
#define K_      16
#define DIN_    64
#define DOUT_   128
#define BN_EPS_ 1e-5f

#define RCTA_   4          // CTAs per batch (cluster size)
#define PPC_    (N_ / RCTA_)   // 2048 points per CTA

// ---------------- scratch (static __device__ — no allocation allowed) ----------------
__device__ int   g_fps_idx[B_ * S_];
__device__ int   g_knn_idx[B_ * S_ * K_];
__device__ float g_h[B_ * N_ * DOUT_];   // 33.5 MB, post MLP+BN+ReLU features

// ---------------- packed f32x2 helpers (exact IEEE per lane) ----------------
__device__ __forceinline__ unsigned long long pack2(float lo, float hi) {
    unsigned long long r;
    asm("mov.b64 %0, {%1, %2};" : "=l"(r) : "f"(lo), "f"(hi));
    return r;
}
__device__ __forceinline__ void unpack2(unsigned long long v, float& lo, float& hi) {
    asm("mov.b64 {%0, %1}, %2;" : "=f"(lo), "=f"(hi) : "l"(v));
}
__device__ __forceinline__ unsigned long long add2(unsigned long long a, unsigned long long b) {
    unsigned long long r;
    asm("add.rn.f32x2 %0, %1, %2;" : "=l"(r) : "l"(a), "l"(b));
    return r;
}
__device__ __forceinline__ unsigned long long mul2(unsigned long long a, unsigned long long b) {
    unsigned long long r;
    asm("mul.rn.f32x2 %0, %1, %2;" : "=l"(r) : "l"(a), "l"(b));
    return r;
}

__device__ __forceinline__ unsigned smem_u32(const void* p) {
    return (unsigned)__cvta_generic_to_shared(p);
}

// ============================================================================
// 1) FPS — cluster of 4 CTAs per batch, each CTA owns 2048 contiguous points
//    (2 per thread). Per iteration:
//      pd update (packed f32x2, exact IEEE order) -> warp REDUX argmax ->
//      one __syncthreads -> warp0 reduces 32 warp slots -> lane0 broadcasts
//      (key, winner coords) to all 4 CTAs via st.shared::cluster + release
//      arrive on each CTA's mbarrier -> all threads acquire-wait, reduce the
//      4 slots locally. key = (val_bits<<32)|~idx : u64 max == (max val,
//      tie min idx), matching jnp.argmax tie-break exactly.
//    Double-buffered slots + two alternating mbarriers (phase-race safe).
// ============================================================================
__global__ __launch_bounds__(1024, 1) __cluster_dims__(RCTA_, 1, 1)
void fps_kernel(const float* __restrict__ coords, float* __restrict__ out_coords)
{
    __shared__ float4 s_pts[PPC_];                    // 32 KB local points
    __shared__ unsigned s_val[2][32], s_idx[2][32];
    __shared__ unsigned long long ex_key[2][RCTA_];
    __shared__ float4 ex_xyz[2][RCTA_];
    __shared__ unsigned long long mbar[2];

    const int b    = blockIdx.x / RCTA_;
    const int rank = blockIdx.x % RCTA_;
    const int t    = threadIdx.x;
    const int lane = t & 31;
    const int w    = t >> 5;
    const float* cb = coords + (size_t)b * N_ * 3;

    const unsigned mbar_a0 = smem_u32(&mbar[0]);
    const unsigned mbar_a1 = smem_u32(&mbar[1]);

    if (t == 0) {
        asm volatile("mbarrier.init.shared.b64 [%0], %1;" :: "r"(mbar_a0), "r"(RCTA_) : "memory");
        asm volatile("mbarrier.init.shared.b64 [%0], %1;" :: "r"(mbar_a1), "r"(RCTA_) : "memory");
    }

    // load my 2 points (2 x 12B = 3 x float2, 8B-aligned)
    unsigned long long pxx, pyy, pzz;
    float pd0, pd1;
    {
        const float2* src = (const float2*)(cb + (size_t)rank * PPC_ * 3 + t * 6);
        float2 a = src[0], bb = src[1], cc = src[2];
        // point0 = (a.x, a.y, b.x), point1 = (b.y, c.x, c.y)
        s_pts[2 * t]     = make_float4(a.x, a.y, bb.x, 0.0f);
        s_pts[2 * t + 1] = make_float4(bb.y, cc.x, cc.y, 0.0f);
        pxx = pack2(a.x, bb.y);
        pyy = pack2(a.y, cc.x);
        pzz = pack2(bb.x, cc.y);
        pd0 = 1e10f; pd1 = 1e10f;
    }

    // initial centroid = global point 0 (every CTA reads it from gmem)
    float4 c = make_float4(cb[0], cb[1], cb[2], 0.0f);
    unsigned g = 0u;

    __syncthreads();
    // cluster-wide: mbarrier init visible before any remote arrive
    asm volatile("barrier.cluster.arrive.aligned;" ::: "memory");
    asm volatile("barrier.cluster.wait.aligned;"   ::: "memory");

    const unsigned FULL = 0xffffffffu;
    const unsigned base = (unsigned)(rank * PPC_ + 2 * t);

    for (int i = 0; i < S_; i++) {
        if (rank == 0 && t == 0) {
            g_fps_idx[b * S_ + i] = (int)g;
            float* oc = out_coords + ((size_t)b * S_ + i) * 3;
            oc[0] = c.x; oc[1] = c.y; oc[2] = c.z;
        }
        if (i == S_ - 1) break;     // no one consumes the next winner

        const int buf = i & 1;
        const unsigned parity = (unsigned)((i >> 1) & 1);

        // ---- distance update (exact IEEE: (p + (-c)), mul, ((x+y)+z)) ----
        {
            unsigned long long ncx = pack2(-c.x, -c.x);
            unsigned long long ncy = pack2(-c.y, -c.y);
            unsigned long long ncz = pack2(-c.z, -c.z);
            unsigned long long dx = add2(pxx, ncx);
            unsigned long long dy = add2(pyy, ncy);
            unsigned long long dz = add2(pzz, ncz);
            unsigned long long dd = add2(add2(mul2(dx, dx), mul2(dy, dy)), mul2(dz, dz));
            float d0, d1;
            unpack2(dd, d0, d1);
            pd0 = fminf(pd0, d0);
            pd1 = fminf(pd1, d1);
        }
        float m = fmaxf(pd0, pd1);
        unsigned mi = (pd0 == m) ? base : (base + 1);   // first-index tie-break

        // ---- warp argmax (dist >= 0 -> float bits order-isomorphic to u32) ----
        unsigned mb = __float_as_uint(m);
        unsigned wm = __reduce_max_sync(FULL, mb);
        unsigned cand = (mb == wm) ? mi : 0xffffffffu;
        unsigned wmi = __reduce_min_sync(FULL, cand);
        if (lane == 0) { s_val[buf][w] = wm; s_idx[buf][w] = wmi; }
        __syncthreads();

        // ---- warp 0: CTA winner + cluster broadcast ----
        if (w == 0) {
            unsigned v  = s_val[buf][lane];
            unsigned ix = s_idx[buf][lane];
            unsigned gm = __reduce_max_sync(FULL, v);
            unsigned c2 = (v == gm) ? ix : 0xffffffffu;
            unsigned gi = __reduce_min_sync(FULL, c2);
            if (lane == 0) {
                unsigned long long key =
                    ((unsigned long long)gm << 32) | (unsigned long long)(~gi);
                float4 wc = s_pts[gi & (PPC_ - 1)];
                unsigned kx = __float_as_uint(wc.x);
                unsigned ky = __float_as_uint(wc.y);
                unsigned kz = __float_as_uint(wc.z);
                unsigned key_l = smem_u32(&ex_key[buf][rank]);
                unsigned xyz_l = smem_u32(&ex_xyz[buf][rank]);
                unsigned mb_l  = (buf == 0) ? mbar_a0 : mbar_a1;
#pragma unroll
                for (int r = 0; r < RCTA_; r++) {
                    unsigned rk, rx, rm;
                    asm("mapa.shared::cluster.u32 %0, %1, %2;" : "=r"(rk) : "r"(key_l), "r"(r));
                    asm("mapa.shared::cluster.u32 %0, %1, %2;" : "=r"(rx) : "r"(xyz_l), "r"(r));
                    asm("mapa.shared::cluster.u32 %0, %1, %2;" : "=r"(rm) : "r"(mb_l),  "r"(r));
                    asm volatile("st.shared::cluster.b64 [%0], %1;" :: "r"(rk), "l"(key) : "memory");
                    asm volatile("st.shared::cluster.v4.b32 [%0], {%1,%2,%3,%4};"
                                 :: "r"(rx), "r"(kx), "r"(ky), "r"(kz), "r"(0u) : "memory");
                    asm volatile("mbarrier.arrive.release.cluster.shared::cluster.b64 _, [%0];"
                                 :: "r"(rm) : "memory");
                }
            }
        }

        // ---- all threads: wait for 4 arrivals, reduce the 4 candidates ----
        {
            unsigned mb_l = (buf == 0) ? mbar_a0 : mbar_a1;
            asm volatile(
                "{\n\t.reg .pred P;\n"
                "WAITL_%=:\n\t"
                "mbarrier.try_wait.parity.acquire.cluster.shared::cta.b64 P, [%0], %1, 0x989680;\n\t"
                "@P bra DONEL_%=;\n\t"
                "bra WAITL_%=;\n"
                "DONEL_%=:\n}"
                :: "r"(mb_l), "r"(parity) : "memory");
        }
        unsigned long long k0 = ex_key[buf][0];
        unsigned long long k1 = ex_key[buf][1];
        unsigned long long k2 = ex_key[buf][2];
        unsigned long long k3 = ex_key[buf][3];
        unsigned long long kk = k0; int wr = 0;
        if (k1 > kk) { kk = k1; wr = 1; }
        if (k2 > kk) { kk = k2; wr = 2; }
        if (k3 > kk) { kk = k3; wr = 3; }
        g = ~((unsigned)kk);
        c = ex_xyz[buf][wr];
    }

    asm volatile("barrier.cluster.arrive.aligned;" ::: "memory");
    asm volatile("barrier.cluster.wait.aligned;"   ::: "memory");
}

// ============================================================================
// 2) KNN: K=16 smallest (d, idx) lexicographic (matches top_k(-d)).
// ============================================================================
__global__ __launch_bounds__(128)
void knn_kernel(const float* __restrict__ coords)
{
    const int b = blockIdx.y;
    const int s = blockIdx.x * 128 + threadIdx.x;
    const float* cb = coords + (size_t)b * N_ * 3;

    const int qi = g_fps_idx[b * S_ + s];
    const float qx = cb[qi * 3 + 0];
    const float qy = cb[qi * 3 + 1];
    const float qz = cb[qi * 3 + 2];

    __shared__ float4 tile[2048];     // 32 KB, padded xyz

    float dk[K_];
    int   ik[K_];
#pragma unroll
    for (int j = 0; j < K_; j++) { dk[j] = CUDART_INF_F; ik[j] = 0; }

    for (int t0 = 0; t0 < N_; t0 += 2048) {
        __syncthreads();
        for (int v = threadIdx.x; v < 2048; v += 128) {
            int p = t0 + v;
            tile[v] = make_float4(cb[p * 3 + 0], cb[p * 3 + 1], cb[p * 3 + 2], 0.0f);
        }
        __syncthreads();

#pragma unroll 8
        for (int p = 0; p < 2048; p++) {
            float4 cc = tile[p];
            float dx = __fsub_rn(qx, cc.x);
            float dy = __fsub_rn(qy, cc.y);
            float dz = __fsub_rn(qz, cc.z);
            float dd = __fadd_rn(__fadd_rn(__fmul_rn(dx, dx), __fmul_rn(dy, dy)),
                                 __fmul_rn(dz, dz));
            if (dd < dk[K_ - 1]) {
                float vd = dd; int vi = t0 + p;
#pragma unroll
                for (int j = 0; j < K_; j++) {
                    if (vd < dk[j]) {
                        float td = dk[j]; int ti = ik[j];
                        dk[j] = vd; ik[j] = vi;
                        vd = td; vi = ti;
                    }
                }
            }
        }
    }

    int* out = &g_knn_idx[((size_t)b * S_ + s) * K_];
#pragma unroll
    for (int j = 0; j < K_; j++) out[j] = ik[j];
}

// ============================================================================
// 3) Pointwise MLP (64->128) + BN(eval) + ReLU on ALL points -> g_h.
// ============================================================================
__global__ __launch_bounds__(256)
void mlp_kernel(const float* __restrict__ features,
                const float* __restrict__ W,
                const float* __restrict__ bias,
                const float* __restrict__ gamma,
                const float* __restrict__ beta,
                const float* __restrict__ rmean,
                const float* __restrict__ rvar)
{
    const int pt0  = blockIdx.x * 32;
    const int o    = threadIdx.x & 127;
    const int half = threadIdx.x >> 7;

    __shared__ float sW[DOUT_ * DIN_];          // 32 KB
    __shared__ float sF[32 * DIN_];             // 8 KB

    for (int v = threadIdx.x; v < DOUT_ * DIN_; v += 256) sW[v] = W[v];
    for (int v = threadIdx.x; v < 32 * DIN_;   v += 256) sF[v] = features[(size_t)pt0 * DIN_ + v];
    __syncthreads();

    float w[DIN_];
#pragma unroll
    for (int d = 0; d < DIN_; d++) w[d] = sW[o * DIN_ + d];

    const float bo = bias[o];
    const float mn = rmean[o];
    const float sc = gamma[o] * rsqrtf(rvar[o] + BN_EPS_);
    const float bt = beta[o];

    for (int p = half * 16; p < half * 16 + 16; p++) {
        float acc = 0.0f;
#pragma unroll
        for (int d = 0; d < DIN_; d += 4) {
            float4 f = *(const float4*)&sF[p * DIN_ + d];
            acc = fmaf(w[d + 0], f.x, acc);
            acc = fmaf(w[d + 1], f.y, acc);
            acc = fmaf(w[d + 2], f.z, acc);
            acc = fmaf(w[d + 3], f.w, acc);
        }
        float lin = acc + bo;
        float val = (lin - mn) * sc + bt;
        g_h[((size_t)pt0 + p) * DOUT_ + o] = fmaxf(val, 0.0f);
    }
}

// ============================================================================
// 4) Gather K neighbors' features + max-pool.
// ============================================================================
__global__ __launch_bounds__(256)
void pool_kernel(float* __restrict__ out_feat)
{
    const int b   = blockIdx.y;
    const int s   = blockIdx.x * 8 + (threadIdx.x >> 5);
    const int col = threadIdx.x & 31;

    const int* kid = &g_knn_idx[((size_t)b * S_ + s) * K_];

    float4 acc = make_float4(-CUDART_INF_F, -CUDART_INF_F, -CUDART_INF_F, -CUDART_INF_F);
#pragma unroll
    for (int k = 0; k < K_; k++) {
        const int id = kid[k];
        const float4 v = *(const float4*)&g_h[((size_t)b * N_ + id) * DOUT_ + col * 4];
        acc.x = fmaxf(acc.x, v.x);
        acc.y = fmaxf(acc.y, v.y);
        acc.z = fmaxf(acc.z, v.z);
        acc.w = fmaxf(acc.w, v.w);
    }
    *(float4*)&out_feat[((size_t)b * S_ + s) * DOUT_ + col * 4] = acc;
}

// ============================================================================
extern "C" void kernel_launch(void* const* d_in, const int* in_sizes, int n_in,
                              void* d_out, int out_size)
{
    const float* coords   = (const float*)d_in[0];
    const float* features = (const float*)d_in[1];
    const float* W        = (const float*)d_in[2];
    const float* bias     = (const float*)d_in[3];
    const float* gamma    = (const float*)d_in[4];
    const float* beta     = (const float*)d_in[5];
    const float* rmean    = (const float*)d_in[6];
    const float* rvar     = (const float*)d_in[7];

    float* out        = (float*)d_out;
    float* out_coords = out;                       // [B, S, 3]
    float* out_feat   = out + (size_t)B_ * S_ * 3; // [B, S, 128]

    fps_kernel<<<B_ * RCTA_, 1024>>>(coords, out_coords);
    mlp_kernel<<<(B_ * N_) / 32, 256>>>(features, W, bias, gamma, beta, rmean, rvar);
    knn_kernel<<<dim3(S_ / 128, B_), 128>>>(coords);
    pool_kernel<<<dim3(S_ / 8, B_), 256>>>(out_feat);
}

// round 5
// speedup vs baseline: 1.9825x; 1.9825x over previous
#include <cuda_runtime.h>
#include <cuda_bf16.h>
#include <math_constants.h>

#define B_      8
#define N_      8192
#define S_      2048
#define K_      16
#define DIN_    64
#define DOUT_   128
#define BN_EPS_ 1e-5f

#define TPB_    512            // FPS threads per CTA
#define PPT_    (N_ / TPB_)    // 16 points per thread

// ---------------- scratch (static __device__ — no allocation allowed) ----------------
__device__ int   g_fps_idx[B_ * S_];
__device__ int   g_knn_idx[B_ * S_ * K_];
__device__ float g_h[B_ * N_ * DOUT_];   // 33.5 MB, post MLP+BN+ReLU features

// ---------------- packed f32x2 helpers (exact IEEE per lane) ----------------
__device__ __forceinline__ unsigned long long pack2(float lo, float hi) {
    unsigned long long r;
    asm("mov.b64 %0, {%1, %2};" : "=l"(r) : "f"(lo), "f"(hi));
    return r;
}
__device__ __forceinline__ void unpack2(unsigned long long v, float& lo, float& hi) {
    asm("mov.b64 {%0, %1}, %2;" : "=f"(lo), "=f"(hi) : "l"(v));
}
__device__ __forceinline__ unsigned long long add2(unsigned long long a, unsigned long long b) {
    unsigned long long r;
    asm("add.rn.f32x2 %0, %1, %2;" : "=l"(r) : "l"(a), "l"(b));
    return r;
}
__device__ __forceinline__ unsigned long long mul2(unsigned long long a, unsigned long long b) {
    unsigned long long r;
    asm("mul.rn.f32x2 %0, %1, %2;" : "=l"(r) : "l"(a), "l"(b));
    return r;
}

// ============================================================================
// 1) FPS — one CTA per batch, 512 threads, 16 contiguous points per thread.
//    Registers hold NEGATED points; (-p)+c == -(p-c) bit-exactly and squaring
//    erases the sign, so distances are bit-identical to the reference's
//    ((p-c)x^2 + (p-c)y^2) + (p-c)z^2 with round-to-nearest at every step.
//    One barrier per iteration; warp argmax via REDUX (float bits of d>=0 are
//    order-isomorphic to u32); ties -> smallest index everywhere (matches
//    jnp.argmax). Winner coords: one broadcast LDS.128 from the smem table.
// ============================================================================
extern __shared__ float4 s_pts[];   // [N_] positive coords, 128 KB

__global__ __launch_bounds__(TPB_, 1)
void fps_kernel(const float* __restrict__ coords, float* __restrict__ out_coords)
{
    __shared__ unsigned s_val[2][32];
    __shared__ unsigned s_idx[2][32];

    const int b = blockIdx.x;
    const int t = threadIdx.x;
    const int lane = t & 31;
    const int w    = t >> 5;
    const float* cb = coords + (size_t)b * N_ * 3;

    unsigned long long npx[8], npy[8], npz[8];   // negated, packed pairs
    float pd[PPT_];

    {
        // thread t owns points 16t..16t+15 = 48 contiguous floats (16B aligned)
        float f[48];
        const float4* src = (const float4*)(cb + t * 48);
#pragma unroll
        for (int q = 0; q < 12; q++) {
            float4 v = src[q];
            f[q * 4 + 0] = v.x; f[q * 4 + 1] = v.y; f[q * 4 + 2] = v.z; f[q * 4 + 3] = v.w;
        }
#pragma unroll
        for (int j = 0; j < PPT_; j++) {
            s_pts[t * PPT_ + j] = make_float4(f[3 * j], f[3 * j + 1], f[3 * j + 2], 0.0f);
            pd[j] = 1e10f;
        }
#pragma unroll
        for (int jj = 0; jj < 8; jj++) {
            npx[jj] = pack2(-f[6 * jj + 0], -f[6 * jj + 3]);
            npy[jj] = pack2(-f[6 * jj + 1], -f[6 * jj + 4]);
            npz[jj] = pack2(-f[6 * jj + 2], -f[6 * jj + 5]);
        }
    }
    // dummy level-2 slots for warps 16..31 (don't exist at 512 threads)
    if (t >= 16 && t < 32) {
        s_val[0][t] = 0u;          s_val[1][t] = 0u;
        s_idx[0][t] = 0xffffffffu; s_idx[1][t] = 0xffffffffu;
    }
    __syncthreads();

    const unsigned FULL = 0xffffffffu;
    unsigned g = 0u;
    float4   c = s_pts[0];
    int buf = 0;

    for (int i = 0; i < S_; i++) {
        if (t == 0) {
            g_fps_idx[b * S_ + i] = (int)g;
            float* oc = out_coords + ((size_t)b * S_ + i) * 3;
            oc[0] = c.x; oc[1] = c.y; oc[2] = c.z;
        }

        const unsigned long long cxx = pack2(c.x, c.x);
        const unsigned long long cyy = pack2(c.y, c.y);
        const unsigned long long czz = pack2(c.z, c.z);

#pragma unroll
        for (int jj = 0; jj < 8; jj++) {
            unsigned long long dx = add2(npx[jj], cxx);    // -(p-c), exact
            unsigned long long dy = add2(npy[jj], cyy);
            unsigned long long dz = add2(npz[jj], czz);
            unsigned long long dd = add2(add2(mul2(dx, dx), mul2(dy, dy)), mul2(dz, dz));
            float d0, d1;
            unpack2(dd, d0, d1);
            pd[2 * jj]     = fminf(pd[2 * jj],     d0);
            pd[2 * jj + 1] = fminf(pd[2 * jj + 1], d1);
        }

        // balanced argmax tree over 16, strict > so ties keep the lower index
        float tv[PPT_]; int ti[PPT_];
#pragma unroll
        for (int j = 0; j < PPT_; j++) { tv[j] = pd[j]; ti[j] = j; }
#pragma unroll
        for (int st = 1; st < PPT_; st <<= 1)
#pragma unroll
            for (int j = 0; j < PPT_; j += 2 * st)
                if (tv[j + st] > tv[j]) { tv[j] = tv[j + st]; ti[j] = ti[j + st]; }
        float m = tv[0];
        unsigned mi = (unsigned)(t * PPT_ + ti[0]);

        // warp argmax (d >= 0 -> float bits order-isomorphic to u32)
        unsigned mb = __float_as_uint(m);
        unsigned wm = __reduce_max_sync(FULL, mb);
        unsigned cand = (mb == wm) ? mi : 0xffffffffu;
        unsigned wmi = __reduce_min_sync(FULL, cand);
        if (lane == 0) { s_val[buf][w] = wm; s_idx[buf][w] = wmi; }
        __syncthreads();

        // every warp reduces the 16 warp results (+16 dummies) itself
        unsigned v  = s_val[buf][lane];
        unsigned ix = s_idx[buf][lane];
        unsigned gm = __reduce_max_sync(FULL, v);
        unsigned c2 = (v == gm) ? ix : 0xffffffffu;
        g = __reduce_min_sync(FULL, c2);
        c = s_pts[g];                 // broadcast LDS.128
        buf ^= 1;
    }
}

// ============================================================================
// 2) KNN: K=16 smallest (d, idx) lexicographic (matches top_k(-d)).
//    1 thread per query, float4-padded smem tiles (1 LDS.128 per point).
// ============================================================================
__global__ __launch_bounds__(128)
void knn_kernel(const float* __restrict__ coords)
{
    const int b = blockIdx.y;
    const int s = blockIdx.x * 128 + threadIdx.x;
    const float* cb = coords + (size_t)b * N_ * 3;

    const int qi = g_fps_idx[b * S_ + s];
    const float qx = cb[qi * 3 + 0];
    const float qy = cb[qi * 3 + 1];
    const float qz = cb[qi * 3 + 2];

    __shared__ float4 tile[2048];     // 32 KB, padded xyz

    float dk[K_];
    int   ik[K_];
#pragma unroll
    for (int j = 0; j < K_; j++) { dk[j] = CUDART_INF_F; ik[j] = 0; }

    for (int t0 = 0; t0 < N_; t0 += 2048) {
        __syncthreads();
        for (int v = threadIdx.x; v < 2048; v += 128) {
            int p = t0 + v;
            tile[v] = make_float4(cb[p * 3 + 0], cb[p * 3 + 1], cb[p * 3 + 2], 0.0f);
        }
        __syncthreads();

#pragma unroll 8
        for (int p = 0; p < 2048; p++) {
            float4 cc = tile[p];
            float dx = __fsub_rn(qx, cc.x);
            float dy = __fsub_rn(qy, cc.y);
            float dz = __fsub_rn(qz, cc.z);
            float dd = __fadd_rn(__fadd_rn(__fmul_rn(dx, dx), __fmul_rn(dy, dy)),
                                 __fmul_rn(dz, dz));
            if (dd < dk[K_ - 1]) {
                float vd = dd; int vi = t0 + p;
#pragma unroll
                for (int j = 0; j < K_; j++) {
                    if (vd < dk[j]) {
                        float td = dk[j]; int ti2 = ik[j];
                        dk[j] = vd; ik[j] = vi;
                        vd = td; vi = ti2;
                    }
                }
            }
        }
    }

    int* out = &g_knn_idx[((size_t)b * S_ + s) * K_];
#pragma unroll
    for (int j = 0; j < K_; j++) out[j] = ik[j];
}

// ============================================================================
// 3) Pointwise MLP (64->128) + BN(eval) + ReLU on ALL points -> g_h.
// ============================================================================
__global__ __launch_bounds__(256)
void mlp_kernel(const float* __restrict__ features,
                const float* __restrict__ W,
                const float* __restrict__ bias,
                const float* __restrict__ gamma,
                const float* __restrict__ beta,
                const float* __restrict__ rmean,
                const float* __restrict__ rvar)
{
    const int pt0  = blockIdx.x * 32;
    const int o    = threadIdx.x & 127;
    const int half = threadIdx.x >> 7;

    __shared__ float sW[DOUT_ * DIN_];          // 32 KB
    __shared__ float sF[32 * DIN_];             // 8 KB

    for (int v = threadIdx.x; v < DOUT_ * DIN_; v += 256) sW[v] = W[v];
    for (int v = threadIdx.x; v < 32 * DIN_;   v += 256) sF[v] = features[(size_t)pt0 * DIN_ + v];
    __syncthreads();

    float w[DIN_];
#pragma unroll
    for (int d = 0; d < DIN_; d++) w[d] = sW[o * DIN_ + d];

    const float bo = bias[o];
    const float mn = rmean[o];
    const float sc = gamma[o] * rsqrtf(rvar[o] + BN_EPS_);
    const float bt = beta[o];

    for (int p = half * 16; p < half * 16 + 16; p++) {
        float acc = 0.0f;
#pragma unroll
        for (int d = 0; d < DIN_; d += 4) {
            float4 f = *(const float4*)&sF[p * DIN_ + d];
            acc = fmaf(w[d + 0], f.x, acc);
            acc = fmaf(w[d + 1], f.y, acc);
            acc = fmaf(w[d + 2], f.z, acc);
            acc = fmaf(w[d + 3], f.w, acc);
        }
        float lin = acc + bo;
        float val = (lin - mn) * sc + bt;
        g_h[((size_t)pt0 + p) * DOUT_ + o] = fmaxf(val, 0.0f);
    }
}

// ============================================================================
// 4) Gather K neighbors' features + max-pool.
// ============================================================================
__global__ __launch_bounds__(256)
void pool_kernel(float* __restrict__ out_feat)
{
    const int b   = blockIdx.y;
    const int s   = blockIdx.x * 8 + (threadIdx.x >> 5);
    const int col = threadIdx.x & 31;

    const int* kid = &g_knn_idx[((size_t)b * S_ + s) * K_];

    float4 acc = make_float4(-CUDART_INF_F, -CUDART_INF_F, -CUDART_INF_F, -CUDART_INF_F);
#pragma unroll
    for (int k = 0; k < K_; k++) {
        const int id = kid[k];
        const float4 v = *(const float4*)&g_h[((size_t)b * N_ + id) * DOUT_ + col * 4];
        acc.x = fmaxf(acc.x, v.x);
        acc.y = fmaxf(acc.y, v.y);
        acc.z = fmaxf(acc.z, v.z);
        acc.w = fmaxf(acc.w, v.w);
    }
    *(float4*)&out_feat[((size_t)b * S_ + s) * DOUT_ + col * 4] = acc;
}

// ============================================================================
extern "C" void kernel_launch(void* const* d_in, const int* in_sizes, int n_in,
                              void* d_out, int out_size)
{
    const float* coords   = (const float*)d_in[0];
    const float* features = (const float*)d_in[1];
    const float* W        = (const float*)d_in[2];
    const float* bias     = (const float*)d_in[3];
    const float* gamma    = (const float*)d_in[4];
    const float* beta     = (const float*)d_in[5];
    const float* rmean    = (const float*)d_in[6];
    const float* rvar     = (const float*)d_in[7];

    float* out        = (float*)d_out;
    float* out_coords = out;                       // [B, S, 3]
    float* out_feat   = out + (size_t)B_ * S_ * 3; // [B, S, 128]

    static bool attr_done = false;
    if (!attr_done) {
        cudaFuncSetAttribute(fps_kernel, cudaFuncAttributeMaxDynamicSharedMemorySize,
                             N_ * (int)sizeof(float4));
        attr_done = true;
    }

    fps_kernel<<<B_, TPB_, N_ * sizeof(float4)>>>(coords, out_coords);
    mlp_kernel<<<(B_ * N_) / 32, 256>>>(features, W, bias, gamma, beta, rmean, rvar);
    knn_kernel<<<dim3(S_ / 128, B_), 128>>>(coords);
    pool_kernel<<<dim3(S_ / 8, B_), 256>>>(out_feat);
}